// round 12
// baseline (speedup 1.0000x reference)
#include <cuda_runtime.h>
#include <cuda_bf16.h>

// LDDMM variational evolve, Gaussian kernel sigma=0.1 (N=8192, D=3).
//   p      = clamp(mom, -1, 1)
//   K_ij   = exp(-50 |x_i - x_j|^2)
//   dcp_i  = sum_j K_ij p_j
//   dmom_i = 100 * ( x_i * row_i - sum_j W_ij x_j ),  W_ij = K_ij (p_i.p_j)
//   row_i  = p_i . dcp_i   (exact linear identity -> epilogue)
//
// R12 = R11 skeleton (TI=128, single 256-pair smem tile, prefetch-1, fused
//       last-CTA reduction) + second i-chain per thread (IPT=2). Each staged
//       j-pair now feeds 4 pair-interactions: the 4 LDS + 2 MUFU + loop
//       overhead amortizes over 2x the work (38 slots/4 pairs vs 46).
//       R10's IPT=2 failed because it ALSO shrank CTAs to 64 threads and broke
//       the pipeline; here only the chain count changes. Grid 32x16=512 CTAs,
//       3.46/SM, single wave; 2 chains/warp keeps ~7 streams/SMSP.

#define TI      128
#define IPT     2
#define IPB     256          // i's per block
#define JP      256          // j-pairs per CTA (= jchunk/2)
#define SPLITJ  16
#define MAXN    8192
#define NBLK    (MAXN/IPB)   // 32 i-blocks
#define L2E     1.4426950408889634f

typedef unsigned long long u64;

// partials: [i][split][8]  (6 used: dcx dcy dcz wxx | wxy wxz)
__device__ float g_part[MAXN * SPLITJ * 8];
__device__ int   g_cnt[NBLK];   // zero-init; self-resetting

__device__ __forceinline__ u64 pack2(float lo, float hi) {
    u64 r; asm("mov.b64 %0, {%1, %2};" : "=l"(r) : "f"(lo), "f"(hi)); return r;
}
__device__ __forceinline__ void unpack2(u64 v, float& lo, float& hi) {
    asm("mov.b64 {%0, %1}, %2;" : "=f"(lo), "=f"(hi) : "l"(v));
}
__device__ __forceinline__ u64 fma2(u64 a, u64 b, u64 c) {
    u64 d; asm("fma.rn.f32x2 %0, %1, %2, %3;" : "=l"(d) : "l"(a), "l"(b), "l"(c)); return d;
}
__device__ __forceinline__ u64 mul2(u64 a, u64 b) {
    u64 d; asm("mul.rn.f32x2 %0, %1, %2;" : "=l"(d) : "l"(a), "l"(b)); return d;
}
__device__ __forceinline__ float ex2a(float x) {
    float y; asm("ex2.approx.f32 %0, %1;" : "=f"(y) : "f"(x)); return y;
}
__device__ __forceinline__ float clamp1(float v) {
    return fminf(fmaxf(v, -1.f), 1.f);
}

__global__ void __launch_bounds__(TI, 5)
lddmm_fused(const float* __restrict__ mom,
            const float* __restrict__ cp,
            float* __restrict__ out,
            int N)
{
    // per j-pair: sA=((x1,x2),(y1,y2))  sB=((z1,z2),(c1,c2))
    //             sC=((px1,px2),(py1,py2))  sZ=(pz1,pz2)
    __shared__ ulonglong2 sA[JP + 1], sB[JP + 1], sC[JP + 1];
    __shared__ u64 sZ[JP + 1];
    __shared__ int sLast;

    const int bx = blockIdx.x;           // i-block
    const int jc = blockIdx.y;           // j-split
    const int j0 = jc * (N / SPLITJ);    // jchunk = 512
    const int tid = threadIdx.x;

    const float c100 = 100.0f * L2E;
    const float cm50 = -50.0f * L2E;

    // per-i state (centered coords), 2 i's per thread
    u64 X0[IPT], X1[IPT], X2[IPT], P0[IPT], P1[IPT], P2[IPT];
    #pragma unroll
    for (int q = 0; q < IPT; q++) {
        int i = bx * IPB + q * TI + tid;
        float xx = cp[3*i+0] - 0.5f, xy = cp[3*i+1] - 0.5f, xz = cp[3*i+2] - 0.5f;
        float px = clamp1(mom[3*i+0]), py = clamp1(mom[3*i+1]), pz = clamp1(mom[3*i+2]);
        X0[q] = pack2(c100 * xx, c100 * xx);
        X1[q] = pack2(c100 * xy, c100 * xy);
        X2[q] = pack2(c100 * xz, c100 * xz);
        P0[q] = pack2(px, px);
        P1[q] = pack2(py, py);
        P2[q] = pack2(pz, pz);
    }

    // stage the full 256-pair tile; thread t handles pairs t and t+TI;
    // thread 0 duplicates pair 0 into the prefetch pad slot [JP].
    #pragma unroll
    for (int t = tid; t < JP; t += TI) {
        int j = j0 + 2 * t;
        float x1 = cp[3*j+0] - 0.5f, y1 = cp[3*j+1] - 0.5f, z1 = cp[3*j+2] - 0.5f;
        float x2 = cp[3*j+3] - 0.5f, y2 = cp[3*j+4] - 0.5f, z2 = cp[3*j+5] - 0.5f;
        float px1 = clamp1(mom[3*j+0]), py1 = clamp1(mom[3*j+1]), pz1 = clamp1(mom[3*j+2]);
        float px2 = clamp1(mom[3*j+3]), py2 = clamp1(mom[3*j+4]), pz2 = clamp1(mom[3*j+5]);
        float c1 = cm50 * fmaf(x1, x1, fmaf(y1, y1, z1 * z1));
        float c2 = cm50 * fmaf(x2, x2, fmaf(y2, y2, z2 * z2));
        ulonglong2 vA = make_ulonglong2(pack2(x1, x2), pack2(y1, y2));
        ulonglong2 vB = make_ulonglong2(pack2(z1, z2), pack2(c1, c2));
        ulonglong2 vC = make_ulonglong2(pack2(px1, px2), pack2(py1, py2));
        u64 vZ = pack2(pz1, pz2);
        sA[t] = vA; sB[t] = vB; sC[t] = vC; sZ[t] = vZ;
        if (t == 0) { sA[JP] = vA; sB[JP] = vB; sC[JP] = vC; sZ[JP] = vZ; }
    }
    __syncthreads();

    u64 awx[IPT], awy[IPT], awz[IPT];   // j-parity sums of w*xj_c
    u64 adx[IPT], ady[IPT], adz[IPT];   // j-parity sums of G*pj_c
    #pragma unroll
    for (int q = 0; q < IPT; q++) {
        awx[q] = awy[q] = awz[q] = 0;
        adx[q] = ady[q] = adz[q] = 0;
    }

    // prefetch-1 pipelined inner loop; each iter feeds both i-chains
    ulonglong2 cA = sA[0], cB = sB[0], cC = sC[0];
    u64 cZ = sZ[0];

    #pragma unroll 4
    for (int k = 0; k < JP; k++) {
        ulonglong2 nA = sA[k+1], nB = sB[k+1], nC = sC[k+1];
        u64 nZ = sZ[k+1];

        #pragma unroll
        for (int q = 0; q < IPT; q++) {
            u64 acc = fma2(X0[q], cA.x, cB.y);   // cj + 144.27*xi.xj
            acc = fma2(X1[q], cA.y, acc);
            acc = fma2(X2[q], cB.x, acc);
            u64 pd = mul2(P0[q], cC.x);          // pi.pj
            pd = fma2(P1[q], cC.y, pd);
            pd = fma2(P2[q], cZ, pd);

            float a1, a2; unpack2(acc, a1, a2);
            u64 Gp = pack2(ex2a(a1), ex2a(a2));  // (G1,G2)
            u64 w  = mul2(Gp, pd);               // (w1,w2)

            awx[q] = fma2(w, cA.x, awx[q]);
            awy[q] = fma2(w, cA.y, awy[q]);
            awz[q] = fma2(w, cB.x, awz[q]);
            adx[q] = fma2(Gp, cC.x, adx[q]);
            ady[q] = fma2(Gp, cC.y, ady[q]);
            adz[q] = fma2(Gp, cZ, adz[q]);
        }

        cA = nA; cB = nB; cC = nC; cZ = nZ;
    }

    // combine j-parity halves, apply Ei (recomputed), store 6-float partial
    #pragma unroll
    for (int q = 0; q < IPT; q++) {
        int i = bx * IPB + q * TI + tid;
        float xx = cp[3*i+0] - 0.5f, xy = cp[3*i+1] - 0.5f, xz = cp[3*i+2] - 0.5f;
        float Ei = ex2a(cm50 * fmaf(xx, xx, fmaf(xy, xy, xz * xz)));
        float u, v;
        unpack2(adx[q], u, v); float dcx = Ei * (u + v);
        unpack2(ady[q], u, v); float dcy = Ei * (u + v);
        unpack2(adz[q], u, v); float dcz = Ei * (u + v);
        unpack2(awx[q], u, v); float wxx = Ei * (u + v);
        unpack2(awy[q], u, v); float wxy = Ei * (u + v);
        unpack2(awz[q], u, v); float wxz = Ei * (u + v);
        float4* p = (float4*)&g_part[(i * SPLITJ + jc) * 8];
        p[0] = make_float4(dcx, dcy, dcz, wxx);
        p[1] = make_float4(wxy, wxz, 0.0f, 0.0f);
    }

    // last CTA per i-block reduces the 16 split partials (fixed order)
    __threadfence();
    __syncthreads();
    if (tid == 0)
        sLast = (atomicAdd(&g_cnt[bx], 1) == SPLITJ - 1) ? 1 : 0;
    __syncthreads();
    if (!sLast) return;
    __threadfence();

    #pragma unroll
    for (int q = 0; q < IPT; q++) {
        int i = bx * IPB + q * TI + tid;
        float4 A = make_float4(0.f, 0.f, 0.f, 0.f);
        float2 B = make_float2(0.f, 0.f);
        #pragma unroll
        for (int s = 0; s < SPLITJ; s++) {
            const float4* p = (const float4*)&g_part[(i * SPLITJ + s) * 8];
            float4 a = p[0], b = p[1];
            A.x += a.x; A.y += a.y; A.z += a.z; A.w += a.w;
            B.x += b.x; B.y += b.y;
        }
        float xx = cp[3*i+0] - 0.5f, xy = cp[3*i+1] - 0.5f, xz = cp[3*i+2] - 0.5f;
        float px = clamp1(mom[3*i+0]), py = clamp1(mom[3*i+1]), pz = clamp1(mom[3*i+2]);
        // row = p_i . dcp_i  (exact linear identity)
        float row = fmaf(px, A.x, fmaf(py, A.y, pz * A.z));
        out[3*i+0] = 100.0f * fmaf(xx, row, -A.w);   // translation-invariant
        out[3*i+1] = 100.0f * fmaf(xy, row, -B.x);
        out[3*i+2] = 100.0f * fmaf(xz, row, -B.y);
        out[3*N + 3*i+0] = A.x;
        out[3*N + 3*i+1] = A.y;
        out[3*N + 3*i+2] = A.z;
    }

    __syncthreads();
    if (tid == 0) g_cnt[bx] = 0;    // reset for next graph replay
}

extern "C" void kernel_launch(void* const* d_in, const int* in_sizes, int n_in,
                              void* d_out, int out_size)
{
    const float* mom = (const float*)d_in[0];
    const float* cp  = (const float*)d_in[1];
    float* out = (float*)d_out;
    int N = in_sizes[0] / 3;   // 8192

    dim3 g(N / IPB, SPLITJ);   // 32 x 16 = 512 CTAs, single resident wave
    lddmm_fused<<<g, TI>>>(mom, cp, out, N);
}

// round 13
// speedup vs baseline: 1.0017x; 1.0017x over previous
#include <cuda_runtime.h>
#include <cuda_bf16.h>

// LDDMM variational evolve, Gaussian kernel sigma=0.1 (N=8192, D=3).
//   p      = clamp(mom, -1, 1)
//   K_ij   = exp(-50 |x_i - x_j|^2)
//   dcp_i  = sum_j K_ij p_j
//   dmom_i = 100 * ( x_i * row_i - sum_j W_ij x_j ),  W_ij = K_ij (p_i.p_j)
//   row_i  = p_i . dcp_i   (exact identity -> epilogue)
//
// R13: R11 was SMEM-CROSSBAR-bound (measured 99K cyc == 7083 warp-iters/SM x
//      14 LDS-cycles; fma demand only 46K). R12 proved IPT=2 halves smem
//      traffic but died on 96-reg occupancy (15.7%). This round: IPT=2 with a
//      lean register budget -- prefetch pipeline removed (ptxas unroll-4 load
//      batching covers LDS latency), Ei recomputed in epilogue,
//      launch_bounds(128,6) = 85-reg cap -> 6 CTAs/SM = 24 warps resident.
//      smem floor 49.6K cyc/SM, fma floor 46K: balanced.
// Grid 32 i-blocks x 32 splits = 1024 CTAs; fused last-CTA reduction.

#define TI      128
#define IPT     2
#define IPB     256          // i's per block
#define JP      128          // j-pairs per CTA tile (jchunk = 256 j's)
#define SPLITJ  32
#define MAXN    8192
#define NBLK    (MAXN/IPB)   // 32 i-blocks
#define L2E     1.4426950408889634f

typedef unsigned long long u64;

// partials: [i][split][8]  (6 used: dcx dcy dcz wxx | wxy wxz)
__device__ float g_part[MAXN * SPLITJ * 8];
__device__ int   g_cnt[NBLK];   // zero-init; self-resetting

__device__ __forceinline__ u64 pack2(float lo, float hi) {
    u64 r; asm("mov.b64 %0, {%1, %2};" : "=l"(r) : "f"(lo), "f"(hi)); return r;
}
__device__ __forceinline__ void unpack2(u64 v, float& lo, float& hi) {
    asm("mov.b64 {%0, %1}, %2;" : "=f"(lo), "=f"(hi) : "l"(v));
}
__device__ __forceinline__ u64 fma2(u64 a, u64 b, u64 c) {
    u64 d; asm("fma.rn.f32x2 %0, %1, %2, %3;" : "=l"(d) : "l"(a), "l"(b), "l"(c)); return d;
}
__device__ __forceinline__ u64 mul2(u64 a, u64 b) {
    u64 d; asm("mul.rn.f32x2 %0, %1, %2;" : "=l"(d) : "l"(a), "l"(b)); return d;
}
__device__ __forceinline__ float ex2a(float x) {
    float y; asm("ex2.approx.f32 %0, %1;" : "=f"(y) : "f"(x)); return y;
}
__device__ __forceinline__ float clamp1(float v) {
    return fminf(fmaxf(v, -1.f), 1.f);
}

__global__ void __launch_bounds__(TI, 6)
lddmm_fused(const float* __restrict__ mom,
            const float* __restrict__ cp,
            float* __restrict__ out,
            int N)
{
    // per j-pair: sA=((x1,x2),(y1,y2))  sB=((z1,z2),(c1,c2))
    //             sC=((px1,px2),(py1,py2))  sZ=(pz1,pz2)
    __shared__ ulonglong2 sA[JP], sB[JP], sC[JP];
    __shared__ u64 sZ[JP];
    __shared__ int sLast;

    const int bx = blockIdx.x;           // i-block
    const int jc = blockIdx.y;           // j-split
    const int j0 = jc * (N / SPLITJ);    // jchunk = 256
    const int tid = threadIdx.x;

    const float c100 = 100.0f * L2E;
    const float cm50 = -50.0f * L2E;

    // per-i state (centered coords), 2 i's per thread
    u64 X0[IPT], X1[IPT], X2[IPT], P0[IPT], P1[IPT], P2[IPT];
    #pragma unroll
    for (int q = 0; q < IPT; q++) {
        int i = bx * IPB + q * TI + tid;
        float xx = cp[3*i+0] - 0.5f, xy = cp[3*i+1] - 0.5f, xz = cp[3*i+2] - 0.5f;
        float px = clamp1(mom[3*i+0]), py = clamp1(mom[3*i+1]), pz = clamp1(mom[3*i+2]);
        X0[q] = pack2(c100 * xx, c100 * xx);
        X1[q] = pack2(c100 * xy, c100 * xy);
        X2[q] = pack2(c100 * xz, c100 * xz);
        P0[q] = pack2(px, px);
        P1[q] = pack2(py, py);
        P2[q] = pack2(pz, pz);
    }

    // stage the 128-pair tile: one pair per thread
    {
        int j = j0 + 2 * tid;
        float x1 = cp[3*j+0] - 0.5f, y1 = cp[3*j+1] - 0.5f, z1 = cp[3*j+2] - 0.5f;
        float x2 = cp[3*j+3] - 0.5f, y2 = cp[3*j+4] - 0.5f, z2 = cp[3*j+5] - 0.5f;
        float px1 = clamp1(mom[3*j+0]), py1 = clamp1(mom[3*j+1]), pz1 = clamp1(mom[3*j+2]);
        float px2 = clamp1(mom[3*j+3]), py2 = clamp1(mom[3*j+4]), pz2 = clamp1(mom[3*j+5]);
        float c1 = cm50 * fmaf(x1, x1, fmaf(y1, y1, z1 * z1));
        float c2 = cm50 * fmaf(x2, x2, fmaf(y2, y2, z2 * z2));
        sA[tid] = make_ulonglong2(pack2(x1, x2), pack2(y1, y2));
        sB[tid] = make_ulonglong2(pack2(z1, z2), pack2(c1, c2));
        sC[tid] = make_ulonglong2(pack2(px1, px2), pack2(py1, py2));
        sZ[tid] = pack2(pz1, pz2);
    }
    __syncthreads();

    u64 awx[IPT], awy[IPT], awz[IPT];   // j-parity sums of w*xj_c
    u64 adx[IPT], ady[IPT], adz[IPT];   // j-parity sums of G*pj_c
    #pragma unroll
    for (int q = 0; q < IPT; q++) {
        awx[q] = awy[q] = awz[q] = 0;
        adx[q] = ady[q] = adz[q] = 0;
    }

    #pragma unroll 4
    for (int k = 0; k < JP; k++) {
        ulonglong2 qa = sA[k];
        ulonglong2 qb = sB[k];
        ulonglong2 qc = sC[k];
        u64 qz = sZ[k];

        #pragma unroll
        for (int q = 0; q < IPT; q++) {
            u64 acc = fma2(X0[q], qa.x, qb.y);   // cj + 144.27*xi.xj
            acc = fma2(X1[q], qa.y, acc);
            acc = fma2(X2[q], qb.x, acc);
            u64 pd = mul2(P0[q], qc.x);          // pi.pj
            pd = fma2(P1[q], qc.y, pd);
            pd = fma2(P2[q], qz, pd);

            float a1, a2; unpack2(acc, a1, a2);
            u64 Gp = pack2(ex2a(a1), ex2a(a2));  // (G1,G2)
            u64 w  = mul2(Gp, pd);               // (w1,w2)

            awx[q] = fma2(w, qa.x, awx[q]);
            awy[q] = fma2(w, qa.y, awy[q]);
            awz[q] = fma2(w, qb.x, awz[q]);
            adx[q] = fma2(Gp, qc.x, adx[q]);
            ady[q] = fma2(Gp, qc.y, ady[q]);
            adz[q] = fma2(Gp, qz, adz[q]);
        }
    }

    // combine j-parity halves, apply Ei (recomputed), store 6-float partial
    #pragma unroll
    for (int q = 0; q < IPT; q++) {
        int i = bx * IPB + q * TI + tid;
        float xx = cp[3*i+0] - 0.5f, xy = cp[3*i+1] - 0.5f, xz = cp[3*i+2] - 0.5f;
        float Ei = ex2a(cm50 * fmaf(xx, xx, fmaf(xy, xy, xz * xz)));
        float u, v;
        unpack2(adx[q], u, v); float dcx = Ei * (u + v);
        unpack2(ady[q], u, v); float dcy = Ei * (u + v);
        unpack2(adz[q], u, v); float dcz = Ei * (u + v);
        unpack2(awx[q], u, v); float wxx = Ei * (u + v);
        unpack2(awy[q], u, v); float wxy = Ei * (u + v);
        unpack2(awz[q], u, v); float wxz = Ei * (u + v);
        float4* p = (float4*)&g_part[(i * SPLITJ + jc) * 8];
        p[0] = make_float4(dcx, dcy, dcz, wxx);
        p[1] = make_float4(wxy, wxz, 0.0f, 0.0f);
    }

    // last CTA per i-block reduces the 32 split partials (fixed order)
    __threadfence();
    __syncthreads();
    if (tid == 0)
        sLast = (atomicAdd(&g_cnt[bx], 1) == SPLITJ - 1) ? 1 : 0;
    __syncthreads();
    if (!sLast) return;
    __threadfence();

    #pragma unroll
    for (int q = 0; q < IPT; q++) {
        int i = bx * IPB + q * TI + tid;
        float4 A = make_float4(0.f, 0.f, 0.f, 0.f);
        float2 B = make_float2(0.f, 0.f);
        #pragma unroll 8
        for (int s = 0; s < SPLITJ; s++) {
            const float4* p = (const float4*)&g_part[(i * SPLITJ + s) * 8];
            float4 a = p[0], b = p[1];
            A.x += a.x; A.y += a.y; A.z += a.z; A.w += a.w;
            B.x += b.x; B.y += b.y;
        }
        float xx = cp[3*i+0] - 0.5f, xy = cp[3*i+1] - 0.5f, xz = cp[3*i+2] - 0.5f;
        float px = clamp1(mom[3*i+0]), py = clamp1(mom[3*i+1]), pz = clamp1(mom[3*i+2]);
        // row = p_i . dcp_i  (exact linear identity)
        float row = fmaf(px, A.x, fmaf(py, A.y, pz * A.z));
        out[3*i+0] = 100.0f * fmaf(xx, row, -A.w);   // translation-invariant
        out[3*i+1] = 100.0f * fmaf(xy, row, -B.x);
        out[3*i+2] = 100.0f * fmaf(xz, row, -B.y);
        out[3*N + 3*i+0] = A.x;
        out[3*N + 3*i+1] = A.y;
        out[3*N + 3*i+2] = A.z;
    }

    __syncthreads();
    if (tid == 0) g_cnt[bx] = 0;    // reset for next graph replay
}

extern "C" void kernel_launch(void* const* d_in, const int* in_sizes, int n_in,
                              void* d_out, int out_size)
{
    const float* mom = (const float*)d_in[0];
    const float* cp  = (const float*)d_in[1];
    float* out = (float*)d_out;
    int N = in_sizes[0] / 3;   // 8192

    dim3 g(N / IPB, SPLITJ);   // 32 x 32 = 1024 CTAs
    lddmm_fused<<<g, TI>>>(mom, cp, out, N);
}

// round 14
// speedup vs baseline: 1.0813x; 1.0795x over previous
#include <cuda_runtime.h>
#include <cuda_bf16.h>

// LDDMM variational evolve, Gaussian kernel sigma=0.1 (N=8192, D=3).
//   p      = clamp(mom, -1, 1)
//   K_ij   = exp(-50 |x_i - x_j|^2)
//   dcp_i  = sum_j K_ij p_j
//   dmom_i = 100 * ( x_i * row_i - sum_j W_ij x_j ),  W_ij = K_ij (p_i.p_j)
//   row_i  = p_i . dcp_i  (exact identity -> epilogue)
//
// R14 = R11 + TWO-STAGE SOFTWARE PIPELINE across ex2. Diagnosis: R8-R13 all
//      ran at "sum of pipe demands, no overlap" (99K cyc == fma 46K + MIO 57K;
//      56 cyc/iter == the serial dot->ex2->accum chain). Stage A(k+1) dot
//      fma2's now issue between stage B(k)'s ex2 issue and consumption, so
//      MUFU latency overlaps fma work. Critical path ~56 -> ~30 cyc/iter.
//      IPT=1, TI=128, prefetch-1, single 128-pair tile, SPLITJ=32 (2048 CTAs),
//      launch_bounds(128,6) for the +6 pipeline registers. Fused reduction.

#define TI      128
#define IPB     128          // i's per block (one i per thread)
#define JP      128          // j-pairs per CTA (jchunk = 256 j's)
#define SPLITJ  32
#define MAXN    8192
#define NBLK    (MAXN/IPB)   // 64 i-blocks
#define L2E     1.4426950408889634f

typedef unsigned long long u64;

// partials: [i][split][8]  (6 used: dcx dcy dcz wxx | wxy wxz)
__device__ float g_part[MAXN * SPLITJ * 8];
__device__ int   g_cnt[NBLK];   // zero-init; self-resetting

__device__ __forceinline__ u64 pack2(float lo, float hi) {
    u64 r; asm("mov.b64 %0, {%1, %2};" : "=l"(r) : "f"(lo), "f"(hi)); return r;
}
__device__ __forceinline__ void unpack2(u64 v, float& lo, float& hi) {
    asm("mov.b64 {%0, %1}, %2;" : "=f"(lo), "=f"(hi) : "l"(v));
}
__device__ __forceinline__ u64 fma2(u64 a, u64 b, u64 c) {
    u64 d; asm("fma.rn.f32x2 %0, %1, %2, %3;" : "=l"(d) : "l"(a), "l"(b), "l"(c)); return d;
}
__device__ __forceinline__ u64 mul2(u64 a, u64 b) {
    u64 d; asm("mul.rn.f32x2 %0, %1, %2;" : "=l"(d) : "l"(a), "l"(b)); return d;
}
__device__ __forceinline__ float ex2a(float x) {
    float y; asm("ex2.approx.f32 %0, %1;" : "=f"(y) : "f"(x)); return y;
}
__device__ __forceinline__ float clamp1(float v) {
    return fminf(fmaxf(v, -1.f), 1.f);
}

__global__ void __launch_bounds__(TI, 6)
lddmm_fused(const float* __restrict__ mom,
            const float* __restrict__ cp,
            float* __restrict__ out,
            int N)
{
    // per j-pair: sA=((x1,x2),(y1,y2))  sB=((z1,z2),(c1,c2))
    //             sC=((px1,px2),(py1,py2))  sZ=(pz1,pz2)
    __shared__ ulonglong2 sA[JP + 1], sB[JP + 1], sC[JP + 1];
    __shared__ u64 sZ[JP + 1];
    __shared__ int sLast;

    const int bx = blockIdx.x;           // i-block
    const int jc = blockIdx.y;           // j-split
    const int j0 = jc * (N / SPLITJ);    // jchunk = 256
    const int tid = threadIdx.x;
    const int i  = bx * IPB + tid;

    const float c100 = 100.0f * L2E;
    const float cm50 = -50.0f * L2E;

    // per-i state (centered coords)
    u64 X0, X1, X2, P0, P1, P2;
    {
        float xx = cp[3*i+0] - 0.5f, xy = cp[3*i+1] - 0.5f, xz = cp[3*i+2] - 0.5f;
        float px = clamp1(mom[3*i+0]), py = clamp1(mom[3*i+1]), pz = clamp1(mom[3*i+2]);
        X0 = pack2(c100 * xx, c100 * xx);
        X1 = pack2(c100 * xy, c100 * xy);
        X2 = pack2(c100 * xz, c100 * xz);
        P0 = pack2(px, px);
        P1 = pack2(py, py);
        P2 = pack2(pz, pz);
    }

    // stage the 128-pair tile: one pair per thread; thread 0 fills pad slot.
    {
        int j = j0 + 2 * tid;
        float x1 = cp[3*j+0] - 0.5f, y1 = cp[3*j+1] - 0.5f, z1 = cp[3*j+2] - 0.5f;
        float x2 = cp[3*j+3] - 0.5f, y2 = cp[3*j+4] - 0.5f, z2 = cp[3*j+5] - 0.5f;
        float px1 = clamp1(mom[3*j+0]), py1 = clamp1(mom[3*j+1]), pz1 = clamp1(mom[3*j+2]);
        float px2 = clamp1(mom[3*j+3]), py2 = clamp1(mom[3*j+4]), pz2 = clamp1(mom[3*j+5]);
        float c1 = cm50 * fmaf(x1, x1, fmaf(y1, y1, z1 * z1));
        float c2 = cm50 * fmaf(x2, x2, fmaf(y2, y2, z2 * z2));
        ulonglong2 vA = make_ulonglong2(pack2(x1, x2), pack2(y1, y2));
        ulonglong2 vB = make_ulonglong2(pack2(z1, z2), pack2(c1, c2));
        ulonglong2 vC = make_ulonglong2(pack2(px1, px2), pack2(py1, py2));
        u64 vZ = pack2(pz1, pz2);
        sA[tid] = vA; sB[tid] = vB; sC[tid] = vC; sZ[tid] = vZ;
        if (tid == 0) { sA[JP] = vA; sB[JP] = vB; sC[JP] = vC; sZ[JP] = vZ; }
    }
    __syncthreads();

    u64 awx = 0, awy = 0, awz = 0;    // j-parity sums of w*xj_c
    u64 adx = 0, ady = 0, adz = 0;    // j-parity sums of G*pj_c

    // ---- two-stage pipeline ----
    // stage A(k): dot products -> (arg1,arg2), pd   (pure fma work)
    // stage B(k): ex2(arg), w = G*pd, 6 accumulations (consumes MUFU result)
    // loop body: issue ex2 for k, run stage A(k+1) under the MUFU latency,
    // then finish stage B(k).
    ulonglong2 cA = sA[0], cB = sB[0], cC = sC[0];
    u64 cZ = sZ[0];
    float a1, a2;
    u64 pd;
    {   // prologue: stage A(0)
        u64 acc = fma2(X0, cA.x, cB.y);
        acc = fma2(X1, cA.y, acc);
        acc = fma2(X2, cB.x, acc);
        pd  = mul2(P0, cC.x);
        pd  = fma2(P1, cC.y, pd);
        pd  = fma2(P2, cZ, pd);
        unpack2(acc, a1, a2);
    }

    #pragma unroll 4
    for (int k = 0; k < JP; k++) {
        // issue MUFU for iter k early
        float K1 = ex2a(a1);
        float K2 = ex2a(a2);

        // prefetch + stage A(k+1) under the MUFU latency
        ulonglong2 nA = sA[k+1], nB = sB[k+1], nC = sC[k+1];
        u64 nZ = sZ[k+1];
        u64 accN = fma2(X0, nA.x, nB.y);
        accN = fma2(X1, nA.y, accN);
        accN = fma2(X2, nB.x, accN);
        u64 pdN = mul2(P0, nC.x);
        pdN = fma2(P1, nC.y, pdN);
        pdN = fma2(P2, nZ, pdN);

        // stage B(k): consume ex2, accumulate with iter-k operands
        u64 Gp = pack2(K1, K2);
        u64 w  = mul2(Gp, pd);
        awx = fma2(w, cA.x, awx);
        awy = fma2(w, cA.y, awy);
        awz = fma2(w, cB.x, awz);
        adx = fma2(Gp, cC.x, adx);
        ady = fma2(Gp, cC.y, ady);
        adz = fma2(Gp, cZ, adz);

        // rotate
        cA = nA; cB = nB; cC = nC; cZ = nZ;
        pd = pdN;
        unpack2(accN, a1, a2);
    }

    // combine j-parity halves, apply Ei (recomputed), store 6-float partial
    {
        float xx = cp[3*i+0] - 0.5f, xy = cp[3*i+1] - 0.5f, xz = cp[3*i+2] - 0.5f;
        float Ei = ex2a(cm50 * fmaf(xx, xx, fmaf(xy, xy, xz * xz)));
        float u, v;
        unpack2(adx, u, v); float dcx = Ei * (u + v);
        unpack2(ady, u, v); float dcy = Ei * (u + v);
        unpack2(adz, u, v); float dcz = Ei * (u + v);
        unpack2(awx, u, v); float wxx = Ei * (u + v);
        unpack2(awy, u, v); float wxy = Ei * (u + v);
        unpack2(awz, u, v); float wxz = Ei * (u + v);
        float4* p = (float4*)&g_part[(i * SPLITJ + jc) * 8];
        p[0] = make_float4(dcx, dcy, dcz, wxx);
        p[1] = make_float4(wxy, wxz, 0.0f, 0.0f);
    }

    // last CTA per i-block reduces the 32 split partials (fixed order)
    __threadfence();
    __syncthreads();
    if (tid == 0)
        sLast = (atomicAdd(&g_cnt[bx], 1) == SPLITJ - 1) ? 1 : 0;
    __syncthreads();
    if (!sLast) return;
    __threadfence();

    {
        float4 A = make_float4(0.f, 0.f, 0.f, 0.f);
        float2 B = make_float2(0.f, 0.f);
        #pragma unroll 8
        for (int s = 0; s < SPLITJ; s++) {
            const float4* p = (const float4*)&g_part[(i * SPLITJ + s) * 8];
            float4 a = p[0], b = p[1];
            A.x += a.x; A.y += a.y; A.z += a.z; A.w += a.w;
            B.x += b.x; B.y += b.y;
        }
        float xx = cp[3*i+0] - 0.5f, xy = cp[3*i+1] - 0.5f, xz = cp[3*i+2] - 0.5f;
        float px = clamp1(mom[3*i+0]), py = clamp1(mom[3*i+1]), pz = clamp1(mom[3*i+2]);
        float row = fmaf(px, A.x, fmaf(py, A.y, pz * A.z));   // p_i . dcp_i
        out[3*i+0] = 100.0f * fmaf(xx, row, -A.w);
        out[3*i+1] = 100.0f * fmaf(xy, row, -B.x);
        out[3*i+2] = 100.0f * fmaf(xz, row, -B.y);
        out[3*N + 3*i+0] = A.x;
        out[3*N + 3*i+1] = A.y;
        out[3*N + 3*i+2] = A.z;
    }

    __syncthreads();
    if (tid == 0) g_cnt[bx] = 0;    // reset for next graph replay
}

extern "C" void kernel_launch(void* const* d_in, const int* in_sizes, int n_in,
                              void* d_out, int out_size)
{
    const float* mom = (const float*)d_in[0];
    const float* cp  = (const float*)d_in[1];
    float* out = (float*)d_out;
    int N = in_sizes[0] / 3;   // 8192

    dim3 g(N / IPB, SPLITJ);   // 64 x 32 = 2048 CTAs
    lddmm_fused<<<g, TI>>>(mom, cp, out, N);
}